// round 8
// baseline (speedup 1.0000x reference)
#include <cuda_runtime.h>
#include <cuda_fp16.h>
#include <cstdint>
#include <cstddef>

typedef unsigned long long u64;
typedef unsigned int u32;

// ---------------------------------------------------------------------------
// Problem shape
// ---------------------------------------------------------------------------
#define B_    4
#define TV_   8192
#define TT_   77
#define C_    1024
#define H_    16
#define D_    64
#define MV    (B_ * TV_)   // 32768
#define MT    (B_ * TT_)   // 308

// ---------------------------------------------------------------------------
// Static fp16 scratch (no device allocation allowed)
// ---------------------------------------------------------------------------
__device__ __half g_vid_h[(size_t)MV * C_];
__device__ __half g_txt_h[(size_t)MT * C_];
__device__ __half g_wq_h[C_ * C_];
__device__ __half g_wk_h[C_ * C_];
__device__ __half g_wv_h[C_ * C_];
__device__ __half g_wo_h[C_ * C_];
__device__ __half g_q_h[(size_t)MV * C_];
__device__ __half g_k_h[(size_t)MT * C_];
__device__ __half g_v_h[(size_t)MT * C_];
__device__ __half g_attn_h[(size_t)MV * C_];

// ---------------------------------------------------------------------------
// PTX helpers (baseline sm_100 — NO tcgen05)
// ---------------------------------------------------------------------------
__device__ __forceinline__ u32 smem_u32(const void* p) {
    u32 a;
    asm("{ .reg .u64 t; cvta.to.shared.u64 t, %1; cvt.u32.u64 %0, t; }"
        : "=r"(a) : "l"(p));
    return a;
}
__device__ __forceinline__ void ldsm_x4(u32 addr, u32* r) {
    asm volatile("ldmatrix.sync.aligned.m8n8.x4.shared.b16 {%0,%1,%2,%3}, [%4];"
                 : "=r"(r[0]), "=r"(r[1]), "=r"(r[2]), "=r"(r[3]) : "r"(addr));
}
__device__ __forceinline__ void ldsm_x4_t(u32 addr, u32* r) {
    asm volatile("ldmatrix.sync.aligned.m8n8.x4.trans.shared.b16 {%0,%1,%2,%3}, [%4];"
                 : "=r"(r[0]), "=r"(r[1]), "=r"(r[2]), "=r"(r[3]) : "r"(addr));
}
__device__ __forceinline__ void mma_f16(float* c, const u32* a, const u32* b) {
    asm volatile(
        "mma.sync.aligned.m16n8k16.row.col.f32.f16.f16.f32 "
        "{%0,%1,%2,%3}, {%4,%5,%6,%7}, {%8,%9}, {%0,%1,%2,%3};"
        : "+f"(c[0]), "+f"(c[1]), "+f"(c[2]), "+f"(c[3])
        : "r"(a[0]), "r"(a[1]), "r"(a[2]), "r"(a[3]), "r"(b[0]), "r"(b[1]));
}
__device__ __forceinline__ void cp16(u32 dst, const void* src, u32 srcsz) {
    asm volatile("cp.async.cg.shared.global [%0], [%1], 16, %2;"
                 :: "r"(dst), "l"(src), "r"(srcsz));
}
__device__ __forceinline__ void cp16f(u32 dst, const void* src) {
    asm volatile("cp.async.cg.shared.global [%0], [%1], 16;"
                 :: "r"(dst), "l"(src));
}
#define CP_COMMIT() asm volatile("cp.async.commit_group;" ::: "memory")
#define CP_WAIT1()  asm volatile("cp.async.wait_group 1;" ::: "memory")

// ---------------------------------------------------------------------------
// fp32 -> fp16 converts, split in two launches (ncu slot alignment):
//   cvt_acts: video + text      cvt_wts: Wq, Wk, Wv, Wo
// ---------------------------------------------------------------------------
#define N4_V  (MV * C_ / 4)
#define N4_T  (MT * C_ / 4)
#define N4_W  (C_ * C_ / 4)
#define ACT_N (N4_V + N4_T)
#define WTS_N (4 * N4_W)

__global__ __launch_bounds__(256)
void cvt_acts(const float* __restrict__ vid, const float* __restrict__ txt)
{
    const int i = blockIdx.x * blockDim.x + threadIdx.x;
    if (i >= ACT_N) return;
    const float* src;
    __half* dst;
    int off;
    if (i < N4_V) { src = vid; dst = g_vid_h; off = i; }
    else          { src = txt; dst = g_txt_h; off = i - N4_V; }
    float4 v = *(const float4*)(src + (size_t)off * 4);
    __half2 a = __floats2half2_rn(v.x, v.y);
    __half2 b = __floats2half2_rn(v.z, v.w);
    *(uint2*)(dst + (size_t)off * 4) = make_uint2(*(u32*)&a, *(u32*)&b);
}

__global__ __launch_bounds__(256)
void cvt_wts(const float* __restrict__ wq, const float* __restrict__ wk,
             const float* __restrict__ wv, const float* __restrict__ wo)
{
    const int i = blockIdx.x * blockDim.x + threadIdx.x;
    if (i >= WTS_N) return;
    const float* src;
    __half* dst;
    int off;
    if (i < N4_W)          { src = wq; dst = g_wq_h; off = i; }
    else if (i < 2 * N4_W) { src = wk; dst = g_wk_h; off = i - N4_W; }
    else if (i < 3 * N4_W) { src = wv; dst = g_wv_h; off = i - 2 * N4_W; }
    else                   { src = wo; dst = g_wo_h; off = i - 3 * N4_W; }
    float4 v = *(const float4*)(src + (size_t)off * 4);
    __half2 a = __floats2half2_rn(v.x, v.y);
    __half2 b = __floats2half2_rn(v.z, v.w);
    *(uint2*)(dst + (size_t)off * 4) = make_uint2(*(u32*)&a, *(u32*)&b);
}

// ---------------------------------------------------------------------------
// fp16 HGEMM (NT): C[M,N] = A[M,K] * B[N,K]^T, fp32 accumulate.
// CTA 128x128, BK=64, 256 threads (8 warps 2x4, warp tile 64x32).
// 4 warps/SMSP for boundary-stall cover; 3-stage cp.async pipeline with
// global prefetch interleaved one chunk-group per k-step (R7 finding:
// stage-start LDGSTS bursts starve the ldsm->mma stream).
// ---------------------------------------------------------------------------
#define HSTR_B   144
#define HTILE_B  (128 * HSTR_B)
#define HSTAGE_B (2 * HTILE_B)
#define HG_DSMEM (3 * HSTAGE_B)    // 110592
#define HTHR     256

// Chunk-group j (0..3): one 16B A chunk + one 16B B chunk per thread.
template <bool FULL_M>
__device__ __forceinline__ void hg_chunk(const __half* __restrict__ A,
                                         const __half* __restrict__ B,
                                         int M, int K, int bm, int bn, int k0,
                                         int tid, u32 sbuf, int j)
{
    const int idx = tid + j * HTHR;
    const int row = idx >> 3, ch = idx & 7;
    if (FULL_M) {
        cp16f(sbuf + (u32)(row * HSTR_B + ch * 16),
              A + (size_t)(bm + row) * K + k0 + ch * 8);
    } else {
        const int gr = bm + row;
        const u32 ssz = (gr < M) ? 16u : 0u;
        const int grc = (gr < M) ? gr : (M - 1);
        cp16(sbuf + (u32)(row * HSTR_B + ch * 16),
             A + (size_t)grc * K + k0 + ch * 8, ssz);
    }
    cp16f(sbuf + (u32)HTILE_B + (u32)(row * HSTR_B + ch * 16),
          B + (size_t)(bn + row) * K + k0 + ch * 8);
}

template <bool FULL_M>
__device__ __forceinline__ void hg_issue_all(const __half* __restrict__ A,
                                             const __half* __restrict__ B,
                                             int M, int K, int bm, int bn,
                                             int k0, int tid, u32 sbuf)
{
#pragma unroll
    for (int j = 0; j < 4; j++)
        hg_chunk<FULL_M>(A, B, M, K, bm, bn, k0, tid, sbuf, j);
}

template <bool FULL_M>
__global__ __launch_bounds__(HTHR, 2)
void hgemm(const __half* __restrict__ A, const __half* __restrict__ B,
           float* __restrict__ Cf, __half* __restrict__ Ch,
           int M, int N, int K)
{
    extern __shared__ char dsm[];
    const u32 sbase = smem_u32(dsm);

    const int tid = threadIdx.x;
    const int lane = tid & 31;
    const int wid = tid >> 5;
    const int wm = wid >> 2;   // 0..1 (64-row slice)
    const int wn = wid & 3;    // 0..3 (32-col slice)
    const int bm = blockIdx.y * 128;
    const int bn = blockIdx.x * 128;

    const u32 a_off = (u32)((((lane & 7) + ((lane >> 3) & 1) * 8) * HSTR_B)
                            + (lane >> 4) * 16);
    const u32 b_off = (u32)((((lane & 7) + ((lane >> 4) & 1) * 8) * HSTR_B)
                            + ((lane >> 3) & 1) * 16);

    float c[4][4][4];
#pragma unroll
    for (int i = 0; i < 4; i++)
#pragma unroll
        for (int j = 0; j < 4; j++)
#pragma unroll
            for (int t = 0; t < 4; t++) c[i][j][t] = 0.f;

    const int S = K / 64;

    hg_issue_all<FULL_M>(A, B, M, K, bm, bn, 0, tid, sbase);
    CP_COMMIT();
    hg_issue_all<FULL_M>(A, B, M, K, bm, bn, 64, tid, sbase + HSTAGE_B);
    CP_COMMIT();

    for (int s = 0; s < S; s++) {
        CP_WAIT1();
        __syncthreads();

        const bool pf = (s + 2 < S);
        const int kpf = (s + 2) * 64;
        const u32 nbuf = sbase + (u32)((s + 2) % 3) * HSTAGE_B;

        const u32 stg = sbase + (u32)(s % 3) * HSTAGE_B;
        const u32 aw = stg + (u32)(wm * 64 * HSTR_B) + a_off;
        const u32 bw = stg + HTILE_B + (u32)(wn * 32 * HSTR_B) + b_off;

#pragma unroll
        for (int ks = 0; ks < 4; ks++) {
            u32 af[4][4], bf[2][4];
            // 1) fragment loads first (feed the tensor pipe)
#pragma unroll
            for (int mf = 0; mf < 4; mf++)
                ldsm_x4(aw + (u32)(mf * 16 * HSTR_B) + (u32)(ks * 32), af[mf]);
#pragma unroll
            for (int nfp = 0; nfp < 2; nfp++)
                ldsm_x4(bw + (u32)(nfp * 16 * HSTR_B) + (u32)(ks * 32), bf[nfp]);
            // 2) one global prefetch chunk-group AFTER the ldsm
            if (pf)
                hg_chunk<FULL_M>(A, B, M, K, bm, bn, kpf, tid, nbuf, ks);
            // 3) mma stream covers the LSU work
#pragma unroll
            for (int mf = 0; mf < 4; mf++)
#pragma unroll
                for (int nf = 0; nf < 4; nf++)
                    mma_f16(c[mf][nf], af[mf], &bf[nf >> 1][(nf & 1) * 2]);
        }
        CP_COMMIT();
    }

    const int cr = lane >> 2;
    const int cc = (lane & 3) * 2;
#pragma unroll
    for (int mf = 0; mf < 4; mf++) {
        const int r0 = bm + wm * 64 + mf * 16 + cr;
#pragma unroll
        for (int nf = 0; nf < 4; nf++) {
            const int col = bn + wn * 32 + nf * 8 + cc;
            if (Ch) {
                if (FULL_M || r0 < M)
                    *(__half2*)(Ch + (size_t)r0 * N + col) =
                        __floats2half2_rn(c[mf][nf][0], c[mf][nf][1]);
                if (FULL_M || r0 + 8 < M)
                    *(__half2*)(Ch + (size_t)(r0 + 8) * N + col) =
                        __floats2half2_rn(c[mf][nf][2], c[mf][nf][3]);
            } else {
                if (FULL_M || r0 < M)
                    *(float2*)(Cf + (size_t)r0 * N + col) =
                        make_float2(c[mf][nf][0], c[mf][nf][1]);
                if (FULL_M || r0 + 8 < M)
                    *(float2*)(Cf + (size_t)(r0 + 8) * N + col) =
                        make_float2(c[mf][nf][2], c[mf][nf][3]);
            }
        }
    }
}

// ---------------------------------------------------------------------------
// Tensor-core attention: block = (b, h, 256 q rows), 8 warps.  (unchanged)
// ---------------------------------------------------------------------------
#define ASTR 72
#define AQROWS 256
#define ATT_SMEMB ((AQROWS * ASTR + 2 * 80 * ASTR) * 2)

__global__ __launch_bounds__(256, 3)
void attention_mma(const __half* __restrict__ Qh, const __half* __restrict__ Kh,
                   const __half* __restrict__ Vh, __half* __restrict__ Oh)
{
    extern __shared__ __half asm_[];
    __half* Qs = asm_;
    __half* Ks = Qs + AQROWS * ASTR;
    __half* Vs = Ks + 80 * ASTR;

    const int tid = threadIdx.x;
    const int lane = tid & 31;
    const int w = tid >> 5;
    const int b = blockIdx.z;
    const int h = blockIdx.y;
    const int t0 = blockIdx.x * AQROWS;

    const __half* qb = Qh + ((size_t)(b * TV_ + t0)) * C_ + h * D_;
    const __half* kb = Kh + (size_t)b * TT_ * C_ + h * D_;
    const __half* vb = Vh + (size_t)b * TT_ * C_ + h * D_;

#pragma unroll
    for (int i = 0; i < 8; i++) {
        const int idx = tid + i * 256;
        const int row = idx >> 3, ch = idx & 7;
        *(uint4*)&Qs[row * ASTR + ch * 8] =
            *(const uint4*)&qb[(size_t)row * C_ + ch * 8];
    }
#pragma unroll
    for (int i = 0; i < 3; i++) {
        const int idx = tid + i * 256;
        if (idx < 640) {
            const int row = idx >> 3, ch = idx & 7;
            uint4 kz = make_uint4(0, 0, 0, 0), vz = make_uint4(0, 0, 0, 0);
            if (row < TT_) {
                kz = *(const uint4*)&kb[(size_t)row * C_ + ch * 8];
                vz = *(const uint4*)&vb[(size_t)row * C_ + ch * 8];
            }
            *(uint4*)&Ks[row * ASTR + ch * 8] = kz;
            *(uint4*)&Vs[row * ASTR + ch * 8] = vz;
        }
    }
    __syncthreads();

    const u32 qsb = smem_u32(Qs), ksb = smem_u32(Ks), vsb = smem_u32(Vs);
    const u32 a_off = (u32)((((lane & 7) + ((lane >> 3) & 1) * 8) * ASTR * 2)
                            + (lane >> 4) * 16);
    const u32 b_off = (u32)((((lane & 7) + ((lane >> 4) & 1) * 8) * ASTR * 2)
                            + ((lane >> 3) & 1) * 16);

    float s[2][10][4];
#pragma unroll
    for (int mf = 0; mf < 2; mf++)
#pragma unroll
        for (int nf = 0; nf < 10; nf++)
#pragma unroll
            for (int j = 0; j < 4; j++) s[mf][nf][j] = 0.f;

#pragma unroll
    for (int ks = 0; ks < 4; ks++) {
        u32 qa[2][4];
#pragma unroll
        for (int mf = 0; mf < 2; mf++)
            ldsm_x4(qsb + (u32)((w * 32 + mf * 16) * ASTR * 2)
                        + (u32)(ks * 32) + a_off, qa[mf]);
#pragma unroll
        for (int nfp = 0; nfp < 5; nfp++) {
            u32 kf[4];
            ldsm_x4(ksb + (u32)(nfp * 16 * ASTR * 2) + (u32)(ks * 32) + b_off, kf);
#pragma unroll
            for (int mf = 0; mf < 2; mf++) {
                mma_f16(s[mf][2 * nfp + 0], qa[mf], &kf[0]);
                mma_f16(s[mf][2 * nfp + 1], qa[mf], &kf[2]);
            }
        }
    }

    const int lq = lane & 3;
    float rsum[2][2] = {{0.f, 0.f}, {0.f, 0.f}};
    u32 p[2][5][4];
#pragma unroll
    for (int mf = 0; mf < 2; mf++) {
#pragma unroll
        for (int nfp = 0; nfp < 5; nfp++) {
#pragma unroll
            for (int part = 0; part < 2; part++) {
                const int nf = 2 * nfp + part;
                const int col = nf * 8 + 2 * lq;
                const bool m0 = (col < TT_);
                const bool m1 = (col + 1 < TT_);
                float e0 = m0 ? __expf(0.125f * s[mf][nf][0]) : 0.f;
                float e1 = m1 ? __expf(0.125f * s[mf][nf][1]) : 0.f;
                float e2 = m0 ? __expf(0.125f * s[mf][nf][2]) : 0.f;
                float e3 = m1 ? __expf(0.125f * s[mf][nf][3]) : 0.f;
                rsum[mf][0] += e0 + e1;
                rsum[mf][1] += e2 + e3;
                __half2 h01 = __floats2half2_rn(e0, e1);
                __half2 h23 = __floats2half2_rn(e2, e3);
                p[mf][nfp][2 * part + 0] = *(u32*)&h01;
                p[mf][nfp][2 * part + 1] = *(u32*)&h23;
            }
        }
    }
    float inv[2][2];
#pragma unroll
    for (int mf = 0; mf < 2; mf++)
#pragma unroll
        for (int j = 0; j < 2; j++) {
            float v = rsum[mf][j];
            v += __shfl_xor_sync(0xFFFFFFFF, v, 1);
            v += __shfl_xor_sync(0xFFFFFFFF, v, 2);
            inv[mf][j] = 1.f / v;
        }

    const int cr = lane >> 2;
#pragma unroll
    for (int nfc = 0; nfc < 2; nfc++) {
        float o[2][4][4];
#pragma unroll
        for (int mf = 0; mf < 2; mf++)
#pragma unroll
            for (int nfi = 0; nfi < 4; nfi++)
#pragma unroll
                for (int j = 0; j < 4; j++) o[mf][nfi][j] = 0.f;

#pragma unroll
        for (int ks = 0; ks < 5; ks++) {
            u32 vf[2][4];
#pragma unroll
            for (int pp = 0; pp < 2; pp++) {
                const int nf0 = nfc * 4 + pp * 2;
                const u32 addr = vsb
                    + (u32)((ks * 16 + (lane & 7) + ((lane >> 3) & 1) * 8) * ASTR * 2)
                    + (u32)(nf0 * 16) + (u32)((lane >> 4) * 16);
                ldsm_x4_t(addr, vf[pp]);
            }
#pragma unroll
            for (int mf = 0; mf < 2; mf++)
#pragma unroll
                for (int nfi = 0; nfi < 4; nfi++)
                    mma_f16(o[mf][nfi], p[mf][ks], &vf[nfi >> 1][(nfi & 1) * 2]);
        }

#pragma unroll
        for (int mf = 0; mf < 2; mf++) {
            const int r0 = t0 + w * 32 + mf * 16 + cr;
#pragma unroll
            for (int nfi = 0; nfi < 4; nfi++) {
                const int col = h * D_ + (nfc * 4 + nfi) * 8 + 2 * lq;
                *(__half2*)(Oh + ((size_t)(b * TV_) + r0) * C_ + col) =
                    __floats2half2_rn(o[mf][nfi][0] * inv[mf][0],
                                      o[mf][nfi][1] * inv[mf][0]);
                *(__half2*)(Oh + ((size_t)(b * TV_) + r0 + 8) * C_ + col) =
                    __floats2half2_rn(o[mf][nfi][2] * inv[mf][1],
                                      o[mf][nfi][3] * inv[mf][1]);
            }
        }
    }
}

// ---------------------------------------------------------------------------
// Launch. attention_mma is launch index 5 (ncu -s5 -c1 captures it).
// ---------------------------------------------------------------------------
extern "C" void kernel_launch(void* const* d_in, const int* in_sizes, int n_in,
                              void* d_out, int out_size)
{
    const float* video = (const float*)d_in[0];
    const float* text  = (const float*)d_in[1];
    const float* Wq    = (const float*)d_in[2];
    const float* Wk    = (const float*)d_in[3];
    const float* Wv    = (const float*)d_in[4];
    const float* Wo    = (const float*)d_in[5];
    float* out = (float*)d_out;

    __half *vid_h, *txt_h, *wq_h, *wk_h, *wv_h, *wo_h, *q_h, *k_h, *v_h, *at_h;
    cudaGetSymbolAddress((void**)&vid_h, g_vid_h);
    cudaGetSymbolAddress((void**)&txt_h, g_txt_h);
    cudaGetSymbolAddress((void**)&wq_h, g_wq_h);
    cudaGetSymbolAddress((void**)&wk_h, g_wk_h);
    cudaGetSymbolAddress((void**)&wv_h, g_wv_h);
    cudaGetSymbolAddress((void**)&wo_h, g_wo_h);
    cudaGetSymbolAddress((void**)&q_h, g_q_h);
    cudaGetSymbolAddress((void**)&k_h, g_k_h);
    cudaGetSymbolAddress((void**)&v_h, g_v_h);
    cudaGetSymbolAddress((void**)&at_h, g_attn_h);

    cudaFuncSetAttribute(hgemm<true>, cudaFuncAttributeMaxDynamicSharedMemorySize,
                         HG_DSMEM);
    cudaFuncSetAttribute(hgemm<false>, cudaFuncAttributeMaxDynamicSharedMemorySize,
                         HG_DSMEM);
    cudaFuncSetAttribute(attention_mma,
                         cudaFuncAttributeMaxDynamicSharedMemorySize, ATT_SMEMB);

    // 0,1: fp32->fp16 conversions
    cvt_acts<<<(ACT_N + 255) / 256, 256>>>(video, text);
    cvt_wts<<<(WTS_N + 255) / 256, 256>>>(Wq, Wk, Wv, Wo);

    // 2,3: K, V projections (partial M)
    hgemm<false><<<dim3(C_ / 128, (MT + 127) / 128), HTHR, HG_DSMEM>>>(
        txt_h, wk_h, nullptr, k_h, MT, C_, C_);
    hgemm<false><<<dim3(C_ / 128, (MT + 127) / 128), HTHR, HG_DSMEM>>>(
        txt_h, wv_h, nullptr, v_h, MT, C_, C_);

    // 4: Q projection
    hgemm<true><<<dim3(C_ / 128, MV / 128), HTHR, HG_DSMEM>>>(
        vid_h, wq_h, nullptr, q_h, MV, C_, C_);

    // 5: fused tensor-core attention  <- ncu captures this one
    attention_mma<<<dim3(TV_ / AQROWS, H_, B_), 256, ATT_SMEMB>>>(
        q_h, k_h, v_h, at_h);

    // 6: output projection (fp32 out)
    hgemm<true><<<dim3(C_ / 128, MV / 128), HTHR, HG_DSMEM>>>(
        at_h, wo_h, out, nullptr, MV, C_, C_);
}